// round 9
// baseline (speedup 1.0000x reference)
#include <cuda_runtime.h>

// Problem constants (fixed by reference setup)
#define RADIUS2f 100.0f            // (2*RQ)^2

constexpr int M  = 50000;          // terrain points
constexpr int Q  = 960;            // 4*6*40 query points
constexpr int BP = 24;             // output elements (B*P)
constexpr int T  = 40;             // trajectory length per (B,P)

constexpr int   GN       = 10;     // grid cells per dim (cell edge == radius)
constexpr float INV_CELL = 0.1f;
constexpr int   NCELL    = GN * GN * GN;   // 1000

constexpr int NT   = 256;
constexpr int NBLK = (M + NT - 1) / NT;    // 196
constexpr int QPT  = (Q + NT - 1) / NT;    // 4 queries stashed per thread

// Fixed-point packed accumulator per query: bits[48..63] = count,
// bits[0..47] = sum(d) * 2^25.  Max sum ~ 50000*10*2^25 < 2^44 -> no carry
// into the count field.  Integer atomics => exactly deterministic.
constexpr float         FIX_SCALE = 33554432.0f;          // 2^25
constexpr float         FIX_INV   = 1.0f / 33554432.0f;
__device__ unsigned long long g_acc[Q];                    // zero at load; reset each call
__device__ unsigned           g_tick = 0;

__global__ __launch_bounds__(NT)
void fused(const float* __restrict__ qg, const float* __restrict__ terr,
           float* __restrict__ out) {
    __shared__ unsigned s_cnt[NCELL];
    __shared__ unsigned s_start[NCELL + 1];
    __shared__ unsigned s_cur[NCELL];
    __shared__ float4   s_q[Q];        // cell-sorted queries (xyz + qi bits)
    __shared__ unsigned s_wsum[8];
    __shared__ float    s_pp[Q];
    __shared__ bool     s_last;

    const int tid = threadIdx.x;
    const int gi  = blockIdx.x * NT + tid;

    // Prefetch this thread's terrain point (independent of query binning).
    float tx = 0.f, ty = 0.f, tz = 0.f;
    const bool have_t = (gi < M);
    if (have_t) { tx = terr[3 * gi]; ty = terr[3 * gi + 1]; tz = terr[3 * gi + 2]; }

    // ---- Build the query grid in SMEM (every block, redundantly) ----
    for (int c = tid; c < NCELL; c += NT) s_cnt[c] = 0;
    __syncthreads();

    float qsx[QPT], qsy[QPT], qsz[QPT];
    int   qcell[QPT], qidx[QPT];
    int   nq = 0;
    for (int qi = tid; qi < Q; qi += NT) {
        const float x = __ldg(qg + 3 * qi + 0);
        const float y = __ldg(qg + 3 * qi + 1);
        const float z = __ldg(qg + 3 * qi + 2);
        const int cx = min(GN - 1, max(0, (int)(x * INV_CELL)));
        const int cy = min(GN - 1, max(0, (int)(y * INV_CELL)));
        const int cz = min(GN - 1, max(0, (int)(z * INV_CELL)));
        const int c  = (cz * GN + cy) * GN + cx;
        atomicAdd(&s_cnt[c], 1u);
        qsx[nq] = x; qsy[nq] = y; qsz[nq] = z; qcell[nq] = c; qidx[nq] = qi; nq++;
    }
    __syncthreads();

    // Exclusive scan of s_cnt[1000] -> s_start (thread t owns cells 4t..4t+3).
    {
        const int t4 = tid * 4;
        unsigned v0 = 0, v1 = 0, v2 = 0, v3 = 0, s = 0;
        if (t4 < NCELL) {
            v0 = s_cnt[t4]; v1 = s_cnt[t4 + 1]; v2 = s_cnt[t4 + 2]; v3 = s_cnt[t4 + 3];
            s = v0 + v1 + v2 + v3;
        }
        const int lane = tid & 31, wid = tid >> 5;
        unsigned incl = s;
#pragma unroll
        for (int o = 1; o < 32; o <<= 1) {
            const unsigned n = __shfl_up_sync(0xffffffffu, incl, o);
            if (lane >= o) incl += n;
        }
        if (lane == 31) s_wsum[wid] = incl;
        __syncthreads();
        if (tid < 8) {
            const unsigned w = s_wsum[tid];
            unsigned wi = w;
#pragma unroll
            for (int o = 1; o < 8; o <<= 1) {
                const unsigned n = __shfl_up_sync(0x000000ffu, wi, o);
                if (tid >= o) wi += n;
            }
            s_wsum[tid] = wi - w;   // exclusive warp offset
        }
        __syncthreads();
        const unsigned base = s_wsum[wid] + (incl - s);
        if (t4 < NCELL) {
            s_start[t4 + 0] = base;
            s_start[t4 + 1] = base + v0;
            s_start[t4 + 2] = base + v0 + v1;
            s_start[t4 + 3] = base + v0 + v1 + v2;
            s_cur[t4 + 0] = s_start[t4 + 0];
            s_cur[t4 + 1] = s_start[t4 + 1];
            s_cur[t4 + 2] = s_start[t4 + 2];
            s_cur[t4 + 3] = s_start[t4 + 3];
        }
        if (tid == 0) s_start[NCELL] = Q;
    }
    __syncthreads();

    // Scatter queries into cell-sorted order.
    for (int j = 0; j < nq; j++) {
        const unsigned slot = atomicAdd(&s_cur[qcell[j]], 1u);
        s_q[slot] = make_float4(qsx[j], qsy[j], qsz[j], __int_as_float(qidx[j]));
    }
    __syncthreads();

    // ---- Terrain phase: one point/thread scans <=27 neighbor cells ----
    if (have_t) {
        const int cx = min(GN - 1, max(0, (int)(tx * INV_CELL)));
        const int cy = min(GN - 1, max(0, (int)(ty * INV_CELL)));
        const int cz = min(GN - 1, max(0, (int)(tz * INV_CELL)));
        const int xlo = max(cx - 1, 0), xhi = min(cx + 1, GN - 1);
        const int ylo = max(cy - 1, 0), yhi = min(cy + 1, GN - 1);
        const int zlo = max(cz - 1, 0), zhi = min(cz + 1, GN - 1);
        for (int zz = zlo; zz <= zhi; zz++)
        for (int yy = ylo; yy <= yhi; yy++) {
            const int c0 = (zz * GN + yy) * GN;
            const unsigned k0 = s_start[c0 + xlo];
            const unsigned k1 = s_start[c0 + xhi + 1];   // x-cells are contiguous
            for (unsigned k = k0; k < k1; k++) {
                const float4 qv = s_q[k];
                const float dx = qv.x - tx, dy = qv.y - ty, dz = qv.z - tz;
                const float d2 = fmaf(dz, dz, fmaf(dy, dy, dx * dx));
                if (d2 <= RADIUS2f) {
                    // Exact-d2 classification (validated R1-R8); approx sqrt
                    // feeds only the sum (rel err ~1e-7 << 1e-3 gate).
                    float d;
                    asm("sqrt.approx.f32 %0, %1;" : "=f"(d) : "f"(d2));
                    const unsigned long long h =
                        (1ULL << 48) + (unsigned long long)__float2ull_rn(d * FIX_SCALE);
                    atomicAdd(&g_acc[__float_as_int(qv.w)], h);
                }
            }
        }
    }

    // ---- Ticket: last block finalizes + resets ----
    __threadfence();
    __syncthreads();
    if (tid == 0) s_last = (atomicAdd(&g_tick, 1u) == (unsigned)(NBLK - 1));
    __syncthreads();
    if (!s_last) return;
    __threadfence();

    for (int qi = tid; qi < Q; qi += NT) {
        const unsigned long long h = *(volatile unsigned long long*)&g_acc[qi];
        const unsigned cnt = (unsigned)(h >> 48);
        float pp = 0.f;
        if (cnt > 0) {
            const float sum = (float)(h & ((1ULL << 48) - 1)) * FIX_INV;
            const float dm  = sum / (float)cnt;
            pp = -(dm * dm) * 0.04f + 4.0f;   // -(dm^2)/RQ^2 + THRESHOLD
        }
        s_pp[qi] = pp;
        g_acc[qi] = 0;                        // reset for next graph replay
    }
    __syncthreads();
    if (tid < BP) {
        float acc = 0.f;
#pragma unroll 8
        for (int t = 0; t < T; t++) acc += s_pp[tid * T + t];
        out[tid] = acc;
    }
    if (tid == 0) g_tick = 0;
}

extern "C" void kernel_launch(void* const* d_in, const int* in_sizes, int n_in,
                              void* d_out, int out_size) {
    // Inputs per metadata order: [traj (960*3), terrain (50000*3)].
    const float* qptr = (const float*)d_in[0];
    const float* tptr = (const float*)d_in[1];
    if (n_in >= 2 && in_sizes[0] == M * 3 && in_sizes[1] == Q * 3) {
        const float* tmp = qptr; qptr = tptr; tptr = tmp;
    }
    float* out = (float*)d_out;

    fused<<<NBLK, NT>>>(qptr, tptr, out);
}